// round 9
// baseline (speedup 1.0000x reference)
#include <cuda_runtime.h>
#include <math.h>

#define BB 8
#define NN 400
#define DD 768
#define CC 3
#define MM 160
#define NPAIR (MM*(MM-1))          // 25440
#define PROB_ELEMS (BB*NPAIR*CC)   // 610560

// ---------------- scratch (static device globals; no allocation) ----------------
__device__ int    g_pos[BB*MM];
__device__ float  g_xr[BB*MM*DD];
__device__ int    g_rr[BB*MM*2];
__device__ float  g_ab[BB*MM*6];   // a[0..2], b[0..2] per (b,m), no bias

// ---------------- K1: fused span dot + rank + position selection ----------------
// one block per batch, 512 threads (16 warps). warp w dots rows w, w+16, ...
__global__ void __launch_bounds__(512)
k_rank(const float* __restrict__ x, const float* __restrict__ w) {
    int b = blockIdx.x;
    __shared__ float s[NN];
    __shared__ int flags[NN];
    __shared__ int wsum[16];
    int t = threadIdx.x;
    int wid = t >> 5, lane = t & 31;

    const float4* wr = (const float4*)w;
    float4 wv[6];
    #pragma unroll
    for (int i = 0; i < 6; i++) wv[i] = wr[i*32 + lane];

    for (int row = wid; row < NN; row += 16) {
        const float4* xr = (const float4*)(x + (size_t)(b*NN + row) * DD);
        float acc = 0.f;
        #pragma unroll
        for (int i = 0; i < 6; i++) {
            float4 v = xr[i*32 + lane];
            acc = fmaf(v.x, wv[i].x, acc);
            acc = fmaf(v.y, wv[i].y, acc);
            acc = fmaf(v.z, wv[i].z, acc);
            acc = fmaf(v.w, wv[i].w, acc);
        }
        #pragma unroll
        for (int o = 16; o; o >>= 1) acc += __shfl_down_sync(0xffffffffu, acc, o);
        if (lane == 0) s[row] = acc;
    }
    if (t < NN) flags[t] = 0;
    __syncthreads();

    if (t < MM) {
        int u = __float_as_int(s[t]);
        unsigned int v = (u < 0) ? ~(unsigned int)u : ((unsigned int)u | 0x80000000u);
        int rank = 0;
        for (int k2 = 0; k2 < NN; k2++) {
            int u2 = __float_as_int(s[k2]);
            unsigned int q = (u2 < 0) ? ~(unsigned int)u2 : ((unsigned int)u2 | 0x80000000u);
            rank += (q > v) || (q == v && k2 < t);
        }
        flags[rank] = 1;
    }
    __syncthreads();
    int f = (t < NN) ? flags[t] : 0;
    unsigned mask = __ballot_sync(0xffffffffu, f);
    if (lane == 0) wsum[wid] = __popc(mask);
    __syncthreads();
    if (t == 0) {
        int run = 0;
        for (int i = 0; i < 16; i++) { int c = wsum[i]; wsum[i] = run; run += c; }
    }
    __syncthreads();
    if (f) {
        int idx = wsum[wid] + __popc(mask & ((1u << lane) - 1));
        g_pos[b*MM + idx] = t;
    }
}

// ---------------- K3: gather x_ranked, ranges, and a/b projections -------------
__global__ void k_gather(const float* __restrict__ x, const float* __restrict__ wp,
                         const int* __restrict__ ranges) {
    int m = blockIdx.x, b = blockIdx.y;
    int p = g_pos[b*MM + m];
    const float4* src = (const float4*)(x + (size_t)(b*NN + p) * DD);
    float4* dst = (float4*)(g_xr + (size_t)(b*MM + m) * DD);
    float acc[6] = {0,0,0,0,0,0};
    for (int t = threadIdx.x; t < DD/4; t += blockDim.x) {
        float4 v = src[t];
        dst[t] = v;
        int d = t * 4;
        float vv[4] = {v.x, v.y, v.z, v.w};
        #pragma unroll
        for (int q = 0; q < 4; q++) {
            #pragma unroll
            for (int c = 0; c < CC; c++) {
                acc[c]     += vv[q] * wp[(d + q) * CC + c];
                acc[3 + c] += vv[q] * wp[(DD + d + q) * CC + c];
            }
        }
    }
    __shared__ float sh[6][4];
    #pragma unroll
    for (int r = 0; r < 6; r++) {
        float a = acc[r];
        #pragma unroll
        for (int o = 16; o; o >>= 1) a += __shfl_down_sync(0xffffffffu, a, o);
        if ((threadIdx.x & 31) == 0) sh[r][threadIdx.x >> 5] = a;
    }
    __syncthreads();
    if (threadIdx.x < 6)
        g_ab[(b*MM + m)*6 + threadIdx.x] =
            sh[threadIdx.x][0] + sh[threadIdx.x][1] + sh[threadIdx.x][2] + sh[threadIdx.x][3];
    if (threadIdx.x < 2)
        g_rr[(b*MM + m)*2 + threadIdx.x] = ranges[p*2 + threadIdx.x];
}

// ---------------- K4: tf32 tensor-core pairwise logits + epilogue --------------
// block tile 16(i) x 32(j), 384 threads (12 warps), in-block k-split x2.
// warp w: kg = w/6 (k8 half), role r = w%6: channel c = r%3, j-half qj=(r/3)*16.
// Packed smem columns: cperm(d) = k8*8 + (d&3)*2 + ((d>>2)&1).
#define TI 16
#define TJ 32
#define KCH 128
#define XS 136     // 136 mod 32 == 8 -> conflict-free LDS.64 pattern

__device__ __forceinline__ void mma_tf32(float* d,
        float a0, float a1, float a2, float a3, float b0, float b1) {
    asm volatile(
        "mma.sync.aligned.m16n8k8.row.col.f32.tf32.tf32.f32 "
        "{%0,%1,%2,%3}, {%4,%5,%6,%7}, {%8,%9}, {%0,%1,%2,%3};\n"
        : "+f"(d[0]), "+f"(d[1]), "+f"(d[2]), "+f"(d[3])
        : "r"(__float_as_uint(a0)), "r"(__float_as_uint(a1)),
          "r"(__float_as_uint(a2)), "r"(__float_as_uint(a3)),
          "r"(__float_as_uint(b0)), "r"(__float_as_uint(b1)));
}

__global__ void __launch_bounds__(384)
k_pairs(const float* __restrict__ wp, const float* __restrict__ bpair,
        float* __restrict__ out) {
    __shared__ float Xi[TI][XS];
    __shared__ float Xj[TJ][XS];
    __shared__ float Ws[CC][KCH];
    __shared__ float Cs[2][CC][TI][TJ + 1];

    int b = blockIdx.y;
    int ibase = (blockIdx.x / 5) * TI;
    int jbase = (blockIdx.x % 5) * TJ;
    int tid = threadIdx.x;
    int wid = tid >> 5, lane = tid & 31;
    int kg = wid / 6;            // k8-half within each chunk
    int role = wid % 6;
    int c  = role % 3;
    int qj = (role / 3) * 16;
    int grp = lane >> 2, tig = lane & 3;

    float acc0[4] = {0,0,0,0};
    float acc1[4] = {0,0,0,0};

    const float* xrb = g_xr + (size_t)b * MM * DD;

    for (int ch = 0; ch < DD / KCH; ch++) {
        int dbase = ch * KCH;
        // load Xi (16 rows) + Xj (32 rows) x 32 float4, permuted scatter
        for (int e = tid; e < (TI + TJ) * (KCH/4); e += 384) {
            int r = e >> 5, c4 = e & 31;
            int d0 = c4 * 4;
            int pos = ((d0 >> 3) << 3) + ((d0 >> 2) & 1);  // k8*8 + half
            float* dstrow = (r < TI) ? Xi[r] : Xj[r - TI];
            const float* srcrow = xrb + (size_t)((r < TI ? ibase + r : jbase + r - TI)) * DD;
            float4 v = *(const float4*)(srcrow + dbase + d0);
            dstrow[pos]     = v.x;
            dstrow[pos + 2] = v.y;
            dstrow[pos + 4] = v.z;
            dstrow[pos + 6] = v.w;
        }
        // load transposed w3 chunk, same permutation (3 x 128 values)
        if (tid < CC * KCH) {
            int cc = tid >> 7, d = tid & 127;
            int pos = ((d >> 3) << 3) + ((d & 3) << 1) + ((d >> 2) & 1);
            Ws[cc][pos] = wp[(2*DD + dbase + d)*CC + cc];
        }
        __syncthreads();

        // this warp's k8 half: [kg*8, kg*8+8)
        #pragma unroll
        for (int k8 = 0; k8 < KCH / 16; k8++) {
            int off = (kg * (KCH/16) + k8) * 8 + tig * 2;
            float2 w  = *(const float2*)&Ws[c][off];
            float2 ai0 = *(const float2*)&Xi[grp][off];
            float2 ai1 = *(const float2*)&Xi[grp + 8][off];
            float2 bj0 = *(const float2*)&Xj[qj + grp][off];
            float2 bj1 = *(const float2*)&Xj[qj + grp + 8][off];
            float a0 = ai0.x * w.x, a1 = ai1.x * w.x;
            float a2 = ai0.y * w.y, a3 = ai1.y * w.y;
            mma_tf32(acc0, a0, a1, a2, a3, bj0.x, bj0.y);
            mma_tf32(acc1, a0, a1, a2, a3, bj1.x, bj1.y);
        }
        __syncthreads();
    }

    // scatter C partials to smem (kg-indexed), summed in the epilogue
    {
        int col = qj + 2*tig;
        Cs[kg][c][grp][col]         = acc0[0];
        Cs[kg][c][grp][col + 1]     = acc0[1];
        Cs[kg][c][grp + 8][col]     = acc0[2];
        Cs[kg][c][grp + 8][col + 1] = acc0[3];
        Cs[kg][c][grp][col + 8]     = acc1[0];
        Cs[kg][c][grp][col + 9]     = acc1[1];
        Cs[kg][c][grp + 8][col + 8] = acc1[2];
        Cs[kg][c][grp + 8][col + 9] = acc1[3];
    }
    __syncthreads();

    float bp0 = bpair[0], bp1 = bpair[1], bp2 = bpair[2];
    #pragma unroll
    for (int p = tid; p < TI * TJ; p += 384) {
        int i = p >> 5, j = p & 31;
        int gi = ibase + i, gj = jbase + j;
        if (gi == gj) continue;
        const float* abI = &g_ab[(b*MM + gi)*6];
        const float* abJ = &g_ab[(b*MM + gj)*6];
        float l0 = Cs[0][0][i][j] + Cs[1][0][i][j] + abI[0] + abJ[3] + bp0;
        float l1 = Cs[0][1][i][j] + Cs[1][1][i][j] + abI[1] + abJ[4] + bp1;
        float l2 = Cs[0][2][i][j] + Cs[1][2][i][j] + abI[2] + abJ[5] + bp2;
        float s0 = 1.f / (1.f + expf(-l0));
        float s1 = 1.f / (1.f + expf(-l1));
        float s2 = 1.f / (1.f + expf(-l2));
        float mx = fmaxf(s0, fmaxf(s1, s2));
        float e0 = expf(s0 - mx), e1 = expf(s1 - mx), e2 = expf(s2 - mx);
        float inv = 1.f / (e0 + e1 + e2);
        int pidx = gi * (MM - 1) + gj - (gj > gi ? 1 : 0);
        size_t po = (size_t)b * NPAIR + pidx;
        float* o = out + po * 3;
        o[0] = e0 * inv; o[1] = e1 * inv; o[2] = e2 * inv;
        const int* ri = &g_rr[(b*MM + gi)*2];
        const int* rj = &g_rr[(b*MM + gj)*2];
        float4 v = make_float4((float)ri[0], (float)ri[1], (float)rj[0], (float)rj[1]);
        ((float4*)(out + PROB_ELEMS))[po] = v;
    }
}

// ---------------- launcher ------------------------------------------------------
extern "C" void kernel_launch(void* const* d_in, const int* in_sizes, int n_in,
                              void* d_out, int out_size) {
    const float* x      = (const float*)d_in[0];
    const float* w_span = (const float*)d_in[1];
    // d_in[2] = b_span (monotonic shift: irrelevant to ordering)
    const float* w_pair = (const float*)d_in[3];
    const float* b_pair = (const float*)d_in[4];
    const int*   ranges = (const int*)d_in[5];
    float* out = (float*)d_out;

    k_rank<<<BB, 512>>>(x, w_span);
    {
        dim3 g(MM, BB);
        k_gather<<<g, 128>>>(x, w_pair, ranges);
    }
    {
        dim3 g(50, BB);   // 10 i-tiles(16) x 5 j-tiles(32)
        k_pairs<<<g, 384>>>(w_pair, b_pair, out);
    }
}

// round 10
// speedup vs baseline: 1.2116x; 1.2116x over previous
#include <cuda_runtime.h>
#include <math.h>

#define BB 8
#define NN 400
#define DD 768
#define CC 3
#define MM 160
#define NPAIR (MM*(MM-1))          // 25440
#define PROB_ELEMS (BB*NPAIR*CC)   // 610560

// ---------------- scratch (static device globals; no allocation) ----------------
__device__ float  g_s[BB*NN];
__device__ int    g_pos[BB*MM];
__device__ float  g_xr[BB*MM*DD];
__device__ int    g_rr[BB*MM*2];
__device__ float  g_ab[BB*MM*6];   // a[0..2], b[0..2] per (b,m), no bias

// ---------------- K1: span dot (f32, warp per row, grid-wide) -------------------
__global__ void k_span(const float* __restrict__ x, const float* __restrict__ w) {
    int row = blockIdx.x * 4 + (threadIdx.x >> 5);   // 0 .. 3199
    int lane = threadIdx.x & 31;
    const float4* xr = (const float4*)(x + (size_t)row * DD);
    const float4* wr = (const float4*)w;
    float acc = 0.f;
    #pragma unroll
    for (int i = 0; i < DD/128; i++) {               // 6 iters
        float4 v = xr[i*32 + lane];
        float4 u = wr[i*32 + lane];
        acc = fmaf(v.x, u.x, acc);
        acc = fmaf(v.y, u.y, acc);
        acc = fmaf(v.z, u.z, acc);
        acc = fmaf(v.w, u.w, acc);
    }
    #pragma unroll
    for (int o = 16; o; o >>= 1) acc += __shfl_down_sync(0xffffffffu, acc, o);
    if (lane == 0) g_s[row] = acc;
}

// ---------------- K2: rank + position selection (uint32 keys, parallel) ---------
__global__ void k_select() {
    int b = blockIdx.x;
    __shared__ unsigned int key[NN];
    __shared__ int flags[NN];
    __shared__ int wsum[16];
    int t = threadIdx.x;     // 512 threads
    if (t < NN) {
        int u = __float_as_int(g_s[b*NN + t]);
        unsigned int k = (u < 0) ? ~(unsigned int)u : ((unsigned int)u | 0x80000000u);
        key[t] = k;
        flags[t] = 0;
    }
    __syncthreads();
    if (t < MM) {
        unsigned int v = key[t];
        int rank = 0;
        for (int k2 = 0; k2 < NN; k2++) {
            unsigned int u = key[k2];
            rank += (u > v) || (u == v && k2 < t);
        }
        flags[rank] = 1;
    }
    __syncthreads();
    int f = (t < NN) ? flags[t] : 0;
    unsigned mask = __ballot_sync(0xffffffffu, f);
    int lane = t & 31, w = t >> 5;
    if (lane == 0) wsum[w] = __popc(mask);
    __syncthreads();
    if (t == 0) {
        int run = 0;
        for (int i = 0; i < 16; i++) { int c = wsum[i]; wsum[i] = run; run += c; }
    }
    __syncthreads();
    if (f) {
        int idx = wsum[w] + __popc(mask & ((1u << lane) - 1));
        g_pos[b*MM + idx] = t;
    }
}

// ---------------- K3: gather x_ranked, ranges, and a/b projections -------------
__global__ void k_gather(const float* __restrict__ x, const float* __restrict__ wp,
                         const int* __restrict__ ranges) {
    int m = blockIdx.x, b = blockIdx.y;
    int p = g_pos[b*MM + m];
    const float4* src = (const float4*)(x + (size_t)(b*NN + p) * DD);
    float4* dst = (float4*)(g_xr + (size_t)(b*MM + m) * DD);
    float acc[6] = {0,0,0,0,0,0};
    for (int t = threadIdx.x; t < DD/4; t += blockDim.x) {
        float4 v = src[t];
        dst[t] = v;
        int d = t * 4;
        float vv[4] = {v.x, v.y, v.z, v.w};
        #pragma unroll
        for (int q = 0; q < 4; q++) {
            #pragma unroll
            for (int c = 0; c < CC; c++) {
                acc[c]     += vv[q] * wp[(d + q) * CC + c];
                acc[3 + c] += vv[q] * wp[(DD + d + q) * CC + c];
            }
        }
    }
    __shared__ float sh[6][4];
    #pragma unroll
    for (int r = 0; r < 6; r++) {
        float a = acc[r];
        #pragma unroll
        for (int o = 16; o; o >>= 1) a += __shfl_down_sync(0xffffffffu, a, o);
        if ((threadIdx.x & 31) == 0) sh[r][threadIdx.x >> 5] = a;
    }
    __syncthreads();
    if (threadIdx.x < 6)
        g_ab[(b*MM + m)*6 + threadIdx.x] =
            sh[threadIdx.x][0] + sh[threadIdx.x][1] + sh[threadIdx.x][2] + sh[threadIdx.x][3];
    if (threadIdx.x < 2)
        g_rr[(b*MM + m)*2 + threadIdx.x] = ranges[p*2 + threadIdx.x];
}

// ---------------- K4: tf32 tensor-core pairwise logits + epilogue --------------
// block tile 16(i) x 32(j), 384 threads (12 warps), in-block k-split x2.
// warp w: kg = w/6 (k8 half), role r = w%6: channel c = r%3, j-half qj=(r/3)*16.
// Packed smem columns: cperm(d) = k8*8 + (d&3)*2 + ((d>>2)&1).
#define TI 16
#define TJ 32
#define KCH 128
#define XS 136     // 136 mod 32 == 8 -> conflict-free LDS.64 pattern

__device__ __forceinline__ void mma_tf32(float* d,
        float a0, float a1, float a2, float a3, float b0, float b1) {
    asm volatile(
        "mma.sync.aligned.m16n8k8.row.col.f32.tf32.tf32.f32 "
        "{%0,%1,%2,%3}, {%4,%5,%6,%7}, {%8,%9}, {%0,%1,%2,%3};\n"
        : "+f"(d[0]), "+f"(d[1]), "+f"(d[2]), "+f"(d[3])
        : "r"(__float_as_uint(a0)), "r"(__float_as_uint(a1)),
          "r"(__float_as_uint(a2)), "r"(__float_as_uint(a3)),
          "r"(__float_as_uint(b0)), "r"(__float_as_uint(b1)));
}

__global__ void __launch_bounds__(384)
k_pairs(const float* __restrict__ wp, const float* __restrict__ bpair,
        float* __restrict__ out) {
    __shared__ float Xi[TI][XS];
    __shared__ float Xj[TJ][XS];
    __shared__ float Ws[CC][KCH];
    __shared__ float Cs[2][CC][TI][TJ + 1];

    int b = blockIdx.y;
    int ibase = (blockIdx.x / 5) * TI;
    int jbase = (blockIdx.x % 5) * TJ;
    int tid = threadIdx.x;
    int wid = tid >> 5, lane = tid & 31;
    int kg = wid / 6;            // k8-half within each chunk
    int role = wid % 6;
    int c  = role % 3;
    int qj = (role / 3) * 16;
    int grp = lane >> 2, tig = lane & 3;

    float acc0[4] = {0,0,0,0};
    float acc1[4] = {0,0,0,0};

    const float* xrb = g_xr + (size_t)b * MM * DD;

    for (int ch = 0; ch < DD / KCH; ch++) {
        int dbase = ch * KCH;
        // load Xi (16 rows) + Xj (32 rows) x 32 float4, permuted scatter
        for (int e = tid; e < (TI + TJ) * (KCH/4); e += 384) {
            int r = e >> 5, c4 = e & 31;
            int d0 = c4 * 4;
            int pos = ((d0 >> 3) << 3) + ((d0 >> 2) & 1);  // k8*8 + half
            float* dstrow = (r < TI) ? Xi[r] : Xj[r - TI];
            const float* srcrow = xrb + (size_t)((r < TI ? ibase + r : jbase + r - TI)) * DD;
            float4 v = *(const float4*)(srcrow + dbase + d0);
            dstrow[pos]     = v.x;
            dstrow[pos + 2] = v.y;
            dstrow[pos + 4] = v.z;
            dstrow[pos + 6] = v.w;
        }
        // load transposed w3 chunk, same permutation (3 x 128 values)
        if (tid < CC * KCH) {
            int cc = tid >> 7, d = tid & 127;
            int pos = ((d >> 3) << 3) + ((d & 3) << 1) + ((d >> 2) & 1);
            Ws[cc][pos] = wp[(2*DD + dbase + d)*CC + cc];
        }
        __syncthreads();

        // this warp's k8 half: [kg*8, kg*8+8)
        #pragma unroll
        for (int k8 = 0; k8 < KCH / 16; k8++) {
            int off = (kg * (KCH/16) + k8) * 8 + tig * 2;
            float2 w  = *(const float2*)&Ws[c][off];
            float2 ai0 = *(const float2*)&Xi[grp][off];
            float2 ai1 = *(const float2*)&Xi[grp + 8][off];
            float2 bj0 = *(const float2*)&Xj[qj + grp][off];
            float2 bj1 = *(const float2*)&Xj[qj + grp + 8][off];
            float a0 = ai0.x * w.x, a1 = ai1.x * w.x;
            float a2 = ai0.y * w.y, a3 = ai1.y * w.y;
            mma_tf32(acc0, a0, a1, a2, a3, bj0.x, bj0.y);
            mma_tf32(acc1, a0, a1, a2, a3, bj1.x, bj1.y);
        }
        __syncthreads();
    }

    // scatter C partials to smem (kg-indexed), summed in the epilogue
    {
        int col = qj + 2*tig;
        Cs[kg][c][grp][col]         = acc0[0];
        Cs[kg][c][grp][col + 1]     = acc0[1];
        Cs[kg][c][grp + 8][col]     = acc0[2];
        Cs[kg][c][grp + 8][col + 1] = acc0[3];
        Cs[kg][c][grp][col + 8]     = acc1[0];
        Cs[kg][c][grp][col + 9]     = acc1[1];
        Cs[kg][c][grp + 8][col + 8] = acc1[2];
        Cs[kg][c][grp + 8][col + 9] = acc1[3];
    }
    __syncthreads();

    float bp0 = bpair[0], bp1 = bpair[1], bp2 = bpair[2];
    #pragma unroll
    for (int p = tid; p < TI * TJ; p += 384) {
        int i = p >> 5, j = p & 31;
        int gi = ibase + i, gj = jbase + j;
        if (gi == gj) continue;
        const float* abI = &g_ab[(b*MM + gi)*6];
        const float* abJ = &g_ab[(b*MM + gj)*6];
        float l0 = Cs[0][0][i][j] + Cs[1][0][i][j] + abI[0] + abJ[3] + bp0;
        float l1 = Cs[0][1][i][j] + Cs[1][1][i][j] + abI[1] + abJ[4] + bp1;
        float l2 = Cs[0][2][i][j] + Cs[1][2][i][j] + abI[2] + abJ[5] + bp2;
        float s0 = 1.f / (1.f + expf(-l0));
        float s1 = 1.f / (1.f + expf(-l1));
        float s2 = 1.f / (1.f + expf(-l2));
        float mx = fmaxf(s0, fmaxf(s1, s2));
        float e0 = expf(s0 - mx), e1 = expf(s1 - mx), e2 = expf(s2 - mx);
        float inv = 1.f / (e0 + e1 + e2);
        int pidx = gi * (MM - 1) + gj - (gj > gi ? 1 : 0);
        size_t po = (size_t)b * NPAIR + pidx;
        float* o = out + po * 3;
        o[0] = e0 * inv; o[1] = e1 * inv; o[2] = e2 * inv;
        const int* ri = &g_rr[(b*MM + gi)*2];
        const int* rj = &g_rr[(b*MM + gj)*2];
        float4 v = make_float4((float)ri[0], (float)ri[1], (float)rj[0], (float)rj[1]);
        ((float4*)(out + PROB_ELEMS))[po] = v;
    }
}

// ---------------- launcher ------------------------------------------------------
extern "C" void kernel_launch(void* const* d_in, const int* in_sizes, int n_in,
                              void* d_out, int out_size) {
    const float* x      = (const float*)d_in[0];
    const float* w_span = (const float*)d_in[1];
    // d_in[2] = b_span (monotonic shift: irrelevant to ordering)
    const float* w_pair = (const float*)d_in[3];
    const float* b_pair = (const float*)d_in[4];
    const int*   ranges = (const int*)d_in[5];
    float* out = (float*)d_out;

    k_span<<<BB * NN / 4, 128>>>(x, w_span);
    k_select<<<BB, 512>>>();
    {
        dim3 g(MM, BB);
        k_gather<<<g, 128>>>(x, w_pair, ranges);
    }
    {
        dim3 g(50, BB);   // 10 i-tiles(16) x 5 j-tiles(32)
        k_pairs<<<g, 384>>>(w_pair, b_pair, out);
    }
}